// round 16
// baseline (speedup 1.0000x reference)
#include <cuda_runtime.h>
#include <cuda_pipeline.h>
#include <cstdint>

// Problem constants
#define BB   64
#define CC   512
#define NN   3000
#define MAXH 70
#define MAXW 40
#define HW   (MAXH * MAXW)        // 2800
#define CPB  8                    // channels per block
#define NT   512                  // threads per block
#define PPT  6                    // ceil(NN / NT)
#define BADCAP 8192

// -------- scratch (no allocations allowed) --------
__device__ int g_badcount = 0;          // reset at END of fixup (persists across graph replays)
__device__ int g_badlist[BADCAP];       // cells where a channel hit exactly -1.0f

// -------- 1) fused gather: per-block map build hidden under ch-0 cp.async ----
__global__ __launch_bounds__(NT) void gather_fused_kernel(
        const float* __restrict__ features,
        const int*   __restrict__ ys,
        const int*   __restrict__ xs,
        float* __restrict__ out) {
    __shared__ __align__(16) int   s_p[HW];        // 11200 B
    __shared__ __align__(16) float s_f[2][NN];     // 2 x 12000 B
    __shared__ int s_mny[16], s_mnx[16], s_mxy[16], s_mxx[16];
    __shared__ int s_swp, s_offr, s_offc;

    const int tid = threadIdx.x;
    const int b   = blockIdx.x / (CC / CPB);
    const int cg  = blockIdx.x % (CC / CPB);
    const size_t bc0 = (size_t)b * CC + (size_t)cg * CPB;

    // ---- kick off channel-0 prefetch FIRST; map build overlaps its flight ----
    {
        const float4* src = (const float4*)(features + bc0 * NN);
        for (int i = tid; i < NN / 4; i += NT)
            __pipeline_memcpy_async(&((float4*)s_f[0])[i], &src[i], 16);
        __pipeline_commit();
    }

    // ---- build cell->point map for this batch (redundant across 32 blocks,
    //      but fully parallel and hidden under the cp.async wait) ----
    for (int i = tid; i < HW / 4; i += NT) {
        int4 e = {-1, -1, -1, -1};
        ((int4*)s_p)[i] = e;
    }
    const int* y = ys + b * NN;
    const int* x = xs + b * NN;
    int ry[PPT], rx[PPT];
    int mny = 0x7fffffff, mnx = 0x7fffffff;
    int mxy = -0x7fffffff, mxx = -0x7fffffff;
    #pragma unroll
    for (int it = 0; it < PPT; it++) {
        int n = tid + it * NT;
        int yy = -1, xx = 0;
        if (n < NN) { yy = __ldg(y + n); xx = __ldg(x + n); }
        ry[it] = yy; rx[it] = xx;
        if (yy > -1) {
            mny = min(mny, yy); mxy = max(mxy, yy);
            mnx = min(mnx, xx); mxx = max(mxx, xx);
        }
    }
    for (int o = 16; o; o >>= 1) {
        mny = min(mny, __shfl_down_sync(0xffffffffu, mny, o));
        mnx = min(mnx, __shfl_down_sync(0xffffffffu, mnx, o));
        mxy = max(mxy, __shfl_down_sync(0xffffffffu, mxy, o));
        mxx = max(mxx, __shfl_down_sync(0xffffffffu, mxx, o));
    }
    int wid = tid >> 5, lid = tid & 31;
    if (lid == 0) { s_mny[wid] = mny; s_mnx[wid] = mnx; s_mxy[wid] = mxy; s_mxx[wid] = mxx; }
    __syncthreads();
    if (tid == 0) {
        for (int w = 1; w < 16; w++) {
            mny = min(mny, s_mny[w]); mnx = min(mnx, s_mnx[w]);
            mxy = max(mxy, s_mxy[w]); mxx = max(mxx, s_mxx[w]);
        }
        int h = mxy - mny + 1;
        int w = mxx - mnx + 1;
        int swp = (w > h) ? 1 : 0;
        int H0 = swp ? w : h;
        int W0 = swp ? h : w;
        int hd = H0 - MAXH;
        int wd = W0 - MAXW;
        int cut_top  = (hd > 0) ? (hd + 1) / 2 : 0;
        int pad_top  = (hd > 0) ? 0 : (1 - hd) / 2;
        int cut_left = (wd > 0) ? (wd + 1) / 2 : 0;
        int left_pad = (wd > 0) ? 0 : (1 - wd) / 2;
        s_swp  = swp;
        s_offr = -(swp ? mnx : mny) - cut_top + pad_top;
        s_offc = -(swp ? mny : mnx) - cut_left + left_pad;
    }
    __syncthreads();
    {
        const int swp = s_swp, offr = s_offr, offc = s_offc;
        #pragma unroll
        for (int it = 0; it < PPT; it++) {
            int yy = ry[it];
            if (yy <= -1) continue;
            int xx = rx[it];
            int rr = (swp ? xx : yy) + offr;
            int cc = (swp ? yy : xx) + offc;
            if (rr >= 0 && rr < MAXH && cc >= 0 && cc < MAXW)
                s_p[rr * MAXW + cc] = tid + it * NT;
        }
    }

    // ---- channel loop (proven structure) ----
    for (int k = 0; k < CPB; k++) {
        const int cur = k & 1;
        __syncthreads();   // readers of buffer cur^1 done; s_p scatter complete at k==0

        if (k + 1 < CPB) { // prefetch next channel into the other buffer
            const float4* src = (const float4*)(features + (bc0 + k + 1) * NN);
            for (int i = tid; i < NN / 4; i += NT)
                __pipeline_memcpy_async(&((float4*)s_f[cur ^ 1])[i], &src[i], 16);
            __pipeline_commit();
            __pipeline_wait_prior(1);    // current buffer's copies landed
        } else {
            __pipeline_wait_prior(0);
        }
        __syncthreads();   // current buffer visible to all threads

        const float* __restrict__ f = s_f[cur];
        float4* __restrict__ dst = (float4*)(out + (bc0 + k) * HW);
        for (int i = tid; i < HW / 4; i += NT) {
            int4 p = ((const int4*)s_p)[i];
            float4 v;
            v.x = (p.x >= 0) ? f[p.x] : 0.0f;
            v.y = (p.y >= 0) ? f[p.y] : 0.0f;
            v.z = (p.z >= 0) ? f[p.z] : 0.0f;
            v.w = (p.w >= 0) ? f[p.w] : 0.0f;
            // exact -1.0f sentinel: append cell to compact list (~Poisson(1.4) hits)
            if (v.x == -1.0f) { int s = atomicAdd(&g_badcount, 1); if (s < BADCAP) g_badlist[s] = b * HW + 4 * i + 0; }
            if (v.y == -1.0f) { int s = atomicAdd(&g_badcount, 1); if (s < BADCAP) g_badlist[s] = b * HW + 4 * i + 1; }
            if (v.z == -1.0f) { int s = atomicAdd(&g_badcount, 1); if (s < BADCAP) g_badlist[s] = b * HW + 4 * i + 2; }
            if (v.w == -1.0f) { int s = atomicAdd(&g_badcount, 1); if (s < BADCAP) g_badlist[s] = b * HW + 4 * i + 3; }
            dst[i] = v;
        }
    }
}

// -------- 2) fixup: zero channels of listed cells; reset counter for next replay ----
__global__ __launch_bounds__(NT) void fixup_kernel(float* __restrict__ out) {
    int cnt = g_badcount;
    if (cnt > BADCAP) cnt = BADCAP;
    for (int j = 0; j < cnt; j++) {           // all threads walk the (tiny) list
        int cell = g_badlist[j];
        int b  = cell / HW;
        int hw = cell - b * HW;
        size_t base = (size_t)b * CC * HW + hw;
        for (int c = threadIdx.x; c < CC; c += NT)
            out[base + (size_t)c * HW] = 0.0f;
    }
    __syncthreads();
    if (threadIdx.x == 0) g_badcount = 0;     // ready for next graph replay
}

extern "C" void kernel_launch(void* const* d_in, const int* in_sizes, int n_in,
                              void* d_out, int out_size) {
    const float* features = (const float*)d_in[0];   // (B, C, N) fp32
    const int*   ys       = (const int*)d_in[1];     // (B, N) int32
    const int*   xs       = (const int*)d_in[2];     // (B, N) int32
    float* out = (float*)d_out;                      // (B, C, 70, 40) fp32

    gather_fused_kernel<<<BB * (CC / CPB), NT>>>(features, ys, xs, out);  // 4096 blocks
    fixup_kernel<<<1, NT>>>(out);
}

// round 17
// speedup vs baseline: 1.0042x; 1.0042x over previous
#include <cuda_runtime.h>
#include <cuda_pipeline.h>
#include <cstdint>

// Problem constants
#define BB   64
#define CC   512
#define NN   3000
#define MAXH 70
#define MAXW 40
#define HW   (MAXH * MAXW)        // 2800
#define CPB  8                    // channels per block
#define NT   512                  // threads per block
#define PPT  6                    // ceil(NN / NT)
#define BADCAP 8192

// -------- scratch (no allocations allowed) --------
__device__ int g_badcount = 0;          // reset at END of fixup (persists across graph replays)
__device__ int g_badlist[BADCAP];       // cells where a channel hit exactly -1.0f

// -------- 1) fused gather: per-block map build hidden under ch-0 cp.async ----
__global__ __launch_bounds__(NT) void gather_fused_kernel(
        const float* __restrict__ features,
        const int*   __restrict__ ys,
        const int*   __restrict__ xs,
        float* __restrict__ out) {
    __shared__ __align__(16) int   s_p[HW];        // 11200 B
    __shared__ __align__(16) float s_f[2][NN];     // 2 x 12000 B
    __shared__ int s_mny[16], s_mnx[16], s_mxy[16], s_mxx[16];
    __shared__ int s_swp, s_offr, s_offc;

    const int tid = threadIdx.x;
    const int b   = blockIdx.x / (CC / CPB);
    const int cg  = blockIdx.x % (CC / CPB);
    const size_t bc0 = (size_t)b * CC + (size_t)cg * CPB;

    // ---- kick off channel-0 prefetch FIRST; map build overlaps its flight ----
    {
        const float4* src = (const float4*)(features + bc0 * NN);
        for (int i = tid; i < NN / 4; i += NT)
            __pipeline_memcpy_async(&((float4*)s_f[0])[i], &src[i], 16);
        __pipeline_commit();
    }

    // ---- build cell->point map for this batch (redundant across 32 blocks,
    //      but fully parallel and hidden under the cp.async wait) ----
    for (int i = tid; i < HW / 4; i += NT) {
        int4 e = {-1, -1, -1, -1};
        ((int4*)s_p)[i] = e;
    }
    const int* y = ys + b * NN;
    const int* x = xs + b * NN;
    int ry[PPT], rx[PPT];
    int mny = 0x7fffffff, mnx = 0x7fffffff;
    int mxy = -0x7fffffff, mxx = -0x7fffffff;
    #pragma unroll
    for (int it = 0; it < PPT; it++) {
        int n = tid + it * NT;
        int yy = -1, xx = 0;
        if (n < NN) { yy = __ldg(y + n); xx = __ldg(x + n); }
        ry[it] = yy; rx[it] = xx;
        if (yy > -1) {
            mny = min(mny, yy); mxy = max(mxy, yy);
            mnx = min(mnx, xx); mxx = max(mxx, xx);
        }
    }
    for (int o = 16; o; o >>= 1) {
        mny = min(mny, __shfl_down_sync(0xffffffffu, mny, o));
        mnx = min(mnx, __shfl_down_sync(0xffffffffu, mnx, o));
        mxy = max(mxy, __shfl_down_sync(0xffffffffu, mxy, o));
        mxx = max(mxx, __shfl_down_sync(0xffffffffu, mxx, o));
    }
    int wid = tid >> 5, lid = tid & 31;
    if (lid == 0) { s_mny[wid] = mny; s_mnx[wid] = mnx; s_mxy[wid] = mxy; s_mxx[wid] = mxx; }
    __syncthreads();
    if (tid == 0) {
        for (int w = 1; w < 16; w++) {
            mny = min(mny, s_mny[w]); mnx = min(mnx, s_mnx[w]);
            mxy = max(mxy, s_mxy[w]); mxx = max(mxx, s_mxx[w]);
        }
        int h = mxy - mny + 1;
        int w = mxx - mnx + 1;
        int swp = (w > h) ? 1 : 0;
        int H0 = swp ? w : h;
        int W0 = swp ? h : w;
        int hd = H0 - MAXH;
        int wd = W0 - MAXW;
        int cut_top  = (hd > 0) ? (hd + 1) / 2 : 0;
        int pad_top  = (hd > 0) ? 0 : (1 - hd) / 2;
        int cut_left = (wd > 0) ? (wd + 1) / 2 : 0;
        int left_pad = (wd > 0) ? 0 : (1 - wd) / 2;
        s_swp  = swp;
        s_offr = -(swp ? mnx : mny) - cut_top + pad_top;
        s_offc = -(swp ? mny : mnx) - cut_left + left_pad;
    }
    __syncthreads();
    {
        const int swp = s_swp, offr = s_offr, offc = s_offc;
        #pragma unroll
        for (int it = 0; it < PPT; it++) {
            int yy = ry[it];
            if (yy <= -1) continue;
            int xx = rx[it];
            int rr = (swp ? xx : yy) + offr;
            int cc = (swp ? yy : xx) + offc;
            if (rr >= 0 && rr < MAXH && cc >= 0 && cc < MAXW)
                s_p[rr * MAXW + cc] = tid + it * NT;
        }
    }

    // ---- channel loop (proven structure) ----
    for (int k = 0; k < CPB; k++) {
        const int cur = k & 1;
        __syncthreads();   // readers of buffer cur^1 done; s_p scatter complete at k==0

        if (k + 1 < CPB) { // prefetch next channel into the other buffer
            const float4* src = (const float4*)(features + (bc0 + k + 1) * NN);
            for (int i = tid; i < NN / 4; i += NT)
                __pipeline_memcpy_async(&((float4*)s_f[cur ^ 1])[i], &src[i], 16);
            __pipeline_commit();
            __pipeline_wait_prior(1);    // current buffer's copies landed
        } else {
            __pipeline_wait_prior(0);
        }
        __syncthreads();   // current buffer visible to all threads

        const float* __restrict__ f = s_f[cur];
        float4* __restrict__ dst = (float4*)(out + (bc0 + k) * HW);
        for (int i = tid; i < HW / 4; i += NT) {
            int4 p = ((const int4*)s_p)[i];
            float4 v;
            v.x = (p.x >= 0) ? f[p.x] : 0.0f;
            v.y = (p.y >= 0) ? f[p.y] : 0.0f;
            v.z = (p.z >= 0) ? f[p.z] : 0.0f;
            v.w = (p.w >= 0) ? f[p.w] : 0.0f;
            // exact -1.0f sentinel: append cell to compact list (~Poisson(1.4) hits)
            if (v.x == -1.0f) { int s = atomicAdd(&g_badcount, 1); if (s < BADCAP) g_badlist[s] = b * HW + 4 * i + 0; }
            if (v.y == -1.0f) { int s = atomicAdd(&g_badcount, 1); if (s < BADCAP) g_badlist[s] = b * HW + 4 * i + 1; }
            if (v.z == -1.0f) { int s = atomicAdd(&g_badcount, 1); if (s < BADCAP) g_badlist[s] = b * HW + 4 * i + 2; }
            if (v.w == -1.0f) { int s = atomicAdd(&g_badcount, 1); if (s < BADCAP) g_badlist[s] = b * HW + 4 * i + 3; }
            dst[i] = v;
        }
    }
}

// -------- 2) fixup: zero channels of listed cells; reset counter for next replay ----
__global__ __launch_bounds__(NT) void fixup_kernel(float* __restrict__ out) {
    int cnt = g_badcount;
    if (cnt > BADCAP) cnt = BADCAP;
    for (int j = 0; j < cnt; j++) {           // all threads walk the (tiny) list
        int cell = g_badlist[j];
        int b  = cell / HW;
        int hw = cell - b * HW;
        size_t base = (size_t)b * CC * HW + hw;
        for (int c = threadIdx.x; c < CC; c += NT)
            out[base + (size_t)c * HW] = 0.0f;
    }
    __syncthreads();
    if (threadIdx.x == 0) g_badcount = 0;     // ready for next graph replay
}

extern "C" void kernel_launch(void* const* d_in, const int* in_sizes, int n_in,
                              void* d_out, int out_size) {
    const float* features = (const float*)d_in[0];   // (B, C, N) fp32
    const int*   ys       = (const int*)d_in[1];     // (B, N) int32
    const int*   xs       = (const int*)d_in[2];     // (B, N) int32
    float* out = (float*)d_out;                      // (B, C, 70, 40) fp32

    gather_fused_kernel<<<BB * (CC / CPB), NT>>>(features, ys, xs, out);  // 4096 blocks
    fixup_kernel<<<1, NT>>>(out);
}